// round 17
// baseline (speedup 1.0000x reference)
#include <cuda_runtime.h>
#include <cstdint>
#include <cstddef>

// ---------------------------------------------------------------------------
// SNN, fp32-faithful, PASSING association (round 9): per output, fp32 FMA
// chain ascending k; K panels [0,512),[512,1024); panel sums combined with
// one rounded add. Schedule-only change this round:
//  * persistent CTAs (grid = 2 x numSMs) + dynamic tile scheduler via a
//    per-launch atomic counter -> kills the 3.46-wave quantization tail
//    (1024 tiles over 296 slots) that R16 still paid (~16%)
//  * per-tile pipeline/epilogue byte-identical to R16 (single-barrier
//    cp.async, k-major operands, stash fold, coalesced epilogue,
//    transposed spike write)
// ---------------------------------------------------------------------------

#define NB 16384
#define NH 1024
#define NSTEPS 25
#define NO 10
#define NTILES 1024    // (NB/128) * (NH/128)

#define KTILE 16
#define SMP 128        // smem row pitch (floats)
#define TP  132        // epilogue tile pitch (floats)
#define SA_BYTES  (2 * KTILE * SMP * 4)            // 16KB
#define SB_BYTES  (2 * KTILE * SMP * 4)            // 16KB
#define STASH_BYTES (128 * TP * 4)                 // 67.6KB >= 64KB u64 stash
#define SMEM_TOTAL (SA_BYTES + SB_BYTES + STASH_BYTES)   // ~98KB

// ----------------------------- device scratch ------------------------------
__device__ __align__(16) float g_spk1aT[NH * NB];
__device__ __align__(16) float g_spk1bT[NH * NB];
__device__ __align__(16) float g_spk2aT[NH * NB];
__device__ __align__(16) float g_spk2bT[NH * NB];
__device__ __align__(16) float g_mem1[NB * NH];
__device__ __align__(16) float g_mem2[NB * NH];
__device__ __align__(16) float g_cur1[NB * NH];
__device__ __align__(16) float g_cur2[NB * NH];
__device__ __align__(16) float g_ssum[NB * NH];
__device__ __align__(16) float g_xT [NH * NB];    // x transposed
__device__ __align__(16) float g_W1T[NH * NH];    // weights [k][n]
__device__ __align__(16) float g_V1T[NH * NH];
__device__ __align__(16) float g_W2T[NH * NH];
__device__ __align__(16) float g_V2T[NH * NH];
__device__ int g_cnt[128];                        // per-launch tile counters

// --------------------------- f32x2 packed helpers ---------------------------
__device__ __forceinline__ uint64_t dup2(float x) {
    uint64_t d;
    asm("mov.b64 %0, {%1, %2};" : "=l"(d) : "f"(x), "f"(x));
    return d;
}
__device__ __forceinline__ uint64_t fma2(uint64_t a, uint64_t b, uint64_t c) {
    uint64_t d;
    asm("fma.rn.f32x2 %0, %1, %2, %3;" : "=l"(d) : "l"(a), "l"(b), "l"(c));
    return d;
}
__device__ __forceinline__ uint64_t add2(uint64_t a, uint64_t b) {
    uint64_t d;
    asm("add.rn.f32x2 %0, %1, %2;" : "=l"(d) : "l"(a), "l"(b));
    return d;
}
__device__ __forceinline__ float2 unpk2(uint64_t v) {
    float lo, hi;
    asm("mov.b64 {%0, %1}, %2;" : "=f"(lo), "=f"(hi) : "l"(v));
    return make_float2(lo, hi);
}
__device__ __forceinline__ uint32_t smem_u32(const void* p) {
    return (uint32_t)__cvta_generic_to_shared(p);
}
__device__ __forceinline__ void cpasync16(uint32_t dst, const void* src) {
    asm volatile("cp.async.cg.shared.global [%0], [%1], 16;\n"
                 :: "r"(dst), "l"(src));
}

// ------------------------------- prep kernels ------------------------------
__global__ void init_state_kernel() {
    size_t i = (size_t)blockIdx.x * blockDim.x + threadIdx.x;
    g_mem1[i] = 0.f;
    g_mem2[i] = 0.f;
    g_ssum[i] = 0.f;
    g_spk1aT[i] = 0.f;
    g_spk2aT[i] = 0.f;
    if (i < 128) g_cnt[i] = 0;
}

__global__ void div25_kernel(float* __restrict__ s) {
    size_t i = (size_t)blockIdx.x * blockDim.x + threadIdx.x;
    s[i] = __fdiv_rn(s[i], 25.0f);
}

// tiled transpose: in [R][C] -> out [C][R]; R, C multiples of 32
__global__ void transpose_kernel(const float* __restrict__ in,
                                 float* __restrict__ out, int R, int C) {
    __shared__ float t[32][33];
    const int c0 = blockIdx.x * 32;
    const int r0 = blockIdx.y * 32;
    const int tx = threadIdx.x;
    const int ty = threadIdx.y;
#pragma unroll
    for (int i = 0; i < 4; i++)
        t[ty + 8 * i][tx] = in[(size_t)(r0 + ty + 8 * i) * C + c0 + tx];
    __syncthreads();
#pragma unroll
    for (int i = 0; i < 4; i++)
        out[(size_t)(c0 + ty + 8 * i) * R + r0 + tx] = t[tx][ty + 8 * i];
}

// ------------------------------- GEMM kernel -------------------------------
// Persistent CTAs pull tiles from cnt. Per tile:
// C[m,n] = sum_k AT[k,m]*BT[k,n]: panels [0,512),[512,1024), serial ascending
// k within panel, one rounded add to combine (EXACTLY as passing R9).
// 256 threads, tile 128x128: warp w -> cols [w*16,+16); lane -> rows [4*lane,+4).

// MODE 0: outC = tot + biasA[n]
// MODE 1: mem = 0.5*mem + cur + tot + biasA - reset; spike -> spkT; [DOSUM]
template <int MODE, int DOSUM>
__global__ void __launch_bounds__(256, 2)
f32gemm_kernel(const float* __restrict__ AT, const float* __restrict__ BT,
               const float* __restrict__ biasA,
               float* __restrict__ memBuf, const float* __restrict__ curBuf,
               float* __restrict__ spkT,
               float* __restrict__ ssum, float* __restrict__ outC,
               int* __restrict__ cnt) {
    extern __shared__ __align__(16) char dsmem[];
    float* sA = (float*)dsmem;                     // [2][KTILE][SMP]
    float* sB = (float*)(dsmem + SA_BYTES);        // [2][KTILE][SMP]
    char*  stashc = dsmem + SA_BYTES + SB_BYTES;
    uint64_t* stash = (uint64_t*)stashc;           // [32][256] during mainloop
    float* tile = (float*)stashc;                  // [128][TP] in epilogue
    __shared__ int sTile;

    const uint32_t sAu = smem_u32(sA);
    const uint32_t sBu = smem_u32(sB);

    const int tid  = threadIdx.x;
    const int warp = tid >> 5;       // 0..7
    const int lane = tid & 31;
    const int nw0  = warp * 16;      // col block for this warp
    const int lm   = lane * 4;       // row block for this lane
    const int nk = NH / KTILE;       // 64

    for (;;) {
        if (tid == 0) sTile = atomicAdd(cnt, 1);
        __syncthreads();
        const int t = sTile;
        if (t >= NTILES) break;
        const int m0 = (t >> 3) * 128;
        const int n0 = (t & 7) * 128;

        uint64_t acc2[4][8];
#pragma unroll
        for (int i = 0; i < 4; i++)
#pragma unroll
            for (int j = 0; j < 8; j++) acc2[i][j] = 0ull;

        // cp.async staging: 2 A + 2 B 16B chunks per thread per k-tile
        auto stage = [&](int kt, int b) {
            const int k0 = kt * KTILE;
#pragma unroll
            for (int j = 0; j < 2; j++) {
                const int chunk = tid + j * 256;
                const int kk = chunk >> 5;
                const int m4 = (chunk & 31) * 4;
                const float* srcA = AT + (size_t)(k0 + kk) * NB + m0 + m4;
                cpasync16(sAu + ((b * KTILE + kk) * SMP + m4) * 4, srcA);
                const float* srcB = BT + (size_t)(k0 + kk) * NH + n0 + m4;
                cpasync16(sBu + ((b * KTILE + kk) * SMP + m4) * 4, srcB);
            }
            asm volatile("cp.async.commit_group;\n");
        };

        stage(0, 0);

        for (int kt = 0; kt < nk; kt++) {
            const int b = kt & 1;
            asm volatile("cp.async.wait_group 0;\n");
            __syncthreads();
            if (kt + 1 < nk) stage(kt + 1, b ^ 1);

            const float* sAb = sA + b * KTILE * SMP;
            const float* sBb = sB + b * KTILE * SMP;
#pragma unroll
            for (int kk = 0; kk < KTILE; kk++) {
                float4 av = *(const float4*)(sAb + kk * SMP + lm);
                uint64_t ad0 = dup2(av.x), ad1 = dup2(av.y);
                uint64_t ad2 = dup2(av.z), ad3 = dup2(av.w);
                const uint64_t* brow = (const uint64_t*)(sBb + kk * SMP + nw0);
#pragma unroll
                for (int q = 0; q < 4; q++) {
                    ulonglong2 bp = *(const ulonglong2*)(brow + 2 * q);
                    const int j0 = 2 * q;
                    acc2[0][j0]     = fma2(ad0, bp.x, acc2[0][j0]);
                    acc2[1][j0]     = fma2(ad1, bp.x, acc2[1][j0]);
                    acc2[2][j0]     = fma2(ad2, bp.x, acc2[2][j0]);
                    acc2[3][j0]     = fma2(ad3, bp.x, acc2[3][j0]);
                    acc2[0][j0 + 1] = fma2(ad0, bp.y, acc2[0][j0 + 1]);
                    acc2[1][j0 + 1] = fma2(ad1, bp.y, acc2[1][j0 + 1]);
                    acc2[2][j0 + 1] = fma2(ad2, bp.y, acc2[2][j0 + 1]);
                    acc2[3][j0 + 1] = fma2(ad3, bp.y, acc2[3][j0 + 1]);
                }
            }

            // panel boundary k=512 (kt 31): stash panel-1 sums, restart acc
            if (kt == 31) {
#pragma unroll
                for (int i = 0; i < 4; i++)
#pragma unroll
                    for (int j = 0; j < 8; j++) {
                        stash[(i * 8 + j) * 256 + tid] = acc2[i][j];
                        acc2[i][j] = 0ull;
                    }
            }
        }

        // ---------------------------- epilogue ------------------------------
        // 1) fold: tot = panel1 + panel2 (one rounded add, as in R9)
        uint64_t tot2[4][8];
#pragma unroll
        for (int i = 0; i < 4; i++)
#pragma unroll
            for (int j = 0; j < 8; j++)
                tot2[i][j] = add2(stash[(i * 8 + j) * 256 + tid], acc2[i][j]);
        __syncthreads();

        // 2) stage tile to smem in (row, col) layout
#pragma unroll
        for (int i = 0; i < 4; i++) {
            const int row = lm + i;
#pragma unroll
            for (int j = 0; j < 8; j++) {
                float2 dv = unpk2(tot2[i][j]);
                *(float2*)&tile[row * TP + nw0 + 2 * j] = dv;
            }
        }
        __syncthreads();

        // 3) coalesced float4 pass: warp -> row, lane -> 4 consecutive cols
#pragma unroll
        for (int it = 0; it < 16; it++) {
            const int row = it * 8 + warp;
            const int col = lane * 4;
            float4 dv = *(const float4*)&tile[row * TP + col];
            const int c = n0 + col;
            const size_t off = (size_t)(m0 + row) * NH + c;
            float4 bias = *(const float4*)&biasA[c];
            if (MODE == 0) {
                float4 o;
                o.x = __fadd_rn(dv.x, bias.x);
                o.y = __fadd_rn(dv.y, bias.y);
                o.z = __fadd_rn(dv.z, bias.z);
                o.w = __fadd_rn(dv.w, bias.w);
                *(float4*)&outC[off] = o;
            } else {
                float4 mo = *(const float4*)&memBuf[off];
                float4 cu = *(const float4*)&curBuf[off];
                float4 nm, sp;
                {
                    // reference order per element:
                    //   mem = ((((0.5*mem) + cur) + d) + bias) - reset(prev)
                    float v;
                    v = __fadd_rn(__fmul_rn(0.5f, mo.x), cu.x);
                    v = __fadd_rn(v, dv.x); v = __fadd_rn(v, bias.x);
                    nm.x = __fsub_rn(v, (mo.x > 1.0f) ? 1.0f : 0.0f);
                    v = __fadd_rn(__fmul_rn(0.5f, mo.y), cu.y);
                    v = __fadd_rn(v, dv.y); v = __fadd_rn(v, bias.y);
                    nm.y = __fsub_rn(v, (mo.y > 1.0f) ? 1.0f : 0.0f);
                    v = __fadd_rn(__fmul_rn(0.5f, mo.z), cu.z);
                    v = __fadd_rn(v, dv.z); v = __fadd_rn(v, bias.z);
                    nm.z = __fsub_rn(v, (mo.z > 1.0f) ? 1.0f : 0.0f);
                    v = __fadd_rn(__fmul_rn(0.5f, mo.w), cu.w);
                    v = __fadd_rn(v, dv.w); v = __fadd_rn(v, bias.w);
                    nm.w = __fsub_rn(v, (mo.w > 1.0f) ? 1.0f : 0.0f);
                }
                *(float4*)&memBuf[off] = nm;
                sp.x = (nm.x > 1.0f) ? 1.0f : 0.0f;
                sp.y = (nm.y > 1.0f) ? 1.0f : 0.0f;
                sp.z = (nm.z > 1.0f) ? 1.0f : 0.0f;
                sp.w = (nm.w > 1.0f) ? 1.0f : 0.0f;
                *(float4*)&tile[row * TP + col] = sp;
                if (DOSUM) {
                    float4 ss = *(const float4*)&ssum[off];
                    ss.x = __fadd_rn(ss.x, sp.x);
                    ss.y = __fadd_rn(ss.y, sp.y);
                    ss.z = __fadd_rn(ss.z, sp.z);
                    ss.w = __fadd_rn(ss.w, sp.w);
                    *(float4*)&ssum[off] = ss;
                }
            }
        }

        // 4) MODE 1: write spikes TRANSPOSED (coalesced along batch)
        if (MODE == 1) {
            __syncthreads();
#pragma unroll
            for (int it = 0; it < 16; it++) {
                const int col = it * 8 + warp;
                const int r4  = lane * 4;
                float4 sp;
                sp.x = tile[(r4 + 0) * TP + col];
                sp.y = tile[(r4 + 1) * TP + col];
                sp.z = tile[(r4 + 2) * TP + col];
                sp.w = tile[(r4 + 3) * TP + col];
                *(float4*)&spkT[(size_t)(n0 + col) * NB + m0 + r4] = sp;
            }
        }
        __syncthreads();   // protect sTile / smem reuse across tiles
    }
}

// ------------------------------ output kernel ------------------------------
__global__ void out_kernel(const float* __restrict__ t,
                           const float* __restrict__ W3,
                           const float* __restrict__ b3,
                           float* __restrict__ out) {
    int idx = blockIdx.x * blockDim.x + threadIdx.x;
    if (idx >= NB * NO) return;
    int row = idx / NO;
    int o   = idx - row * NO;
    const float* tr = t  + (size_t)row * NH;
    const float* wr = W3 + (size_t)o * NH;
    float acc = 0.f;
#pragma unroll 8
    for (int k = 0; k < NH; k++)
        acc = fmaf(__ldg(&tr[k]), __ldg(&wr[k]), acc);
    out[idx] = __fadd_rn(acc, b3[o]);
}

// ------------------------------- host launch -------------------------------
extern "C" void kernel_launch(void* const* d_in, const int* in_sizes, int n_in,
                              void* d_out, int out_size) {
    const float* x   = (const float*)d_in[0];
    const float* W1  = (const float*)d_in[1];
    const float* b1  = (const float*)d_in[2];
    const float* V1w = (const float*)d_in[3];
    const float* V1b = (const float*)d_in[4];
    const float* W2  = (const float*)d_in[5];
    const float* b2  = (const float*)d_in[6];
    const float* V2w = (const float*)d_in[7];
    const float* V2b = (const float*)d_in[8];
    const float* W3  = (const float*)d_in[9];
    const float* b3  = (const float*)d_in[10];
    float* out = (float*)d_out;

    void* p;
    float *s1aT, *s1bT, *s2aT, *s2bT, *mem1, *mem2, *cur1, *cur2, *ssum;
    float *xT, *w1T, *v1T, *w2T, *v2T;
    int* cnt;
    cudaGetSymbolAddress(&p, g_spk1aT); s1aT = (float*)p;
    cudaGetSymbolAddress(&p, g_spk1bT); s1bT = (float*)p;
    cudaGetSymbolAddress(&p, g_spk2aT); s2aT = (float*)p;
    cudaGetSymbolAddress(&p, g_spk2bT); s2bT = (float*)p;
    cudaGetSymbolAddress(&p, g_mem1);   mem1 = (float*)p;
    cudaGetSymbolAddress(&p, g_mem2);   mem2 = (float*)p;
    cudaGetSymbolAddress(&p, g_cur1);   cur1 = (float*)p;
    cudaGetSymbolAddress(&p, g_cur2);   cur2 = (float*)p;
    cudaGetSymbolAddress(&p, g_ssum);   ssum = (float*)p;
    cudaGetSymbolAddress(&p, g_xT);     xT   = (float*)p;
    cudaGetSymbolAddress(&p, g_W1T);    w1T  = (float*)p;
    cudaGetSymbolAddress(&p, g_V1T);    v1T  = (float*)p;
    cudaGetSymbolAddress(&p, g_W2T);    w2T  = (float*)p;
    cudaGetSymbolAddress(&p, g_V2T);    v2T  = (float*)p;
    cudaGetSymbolAddress(&p, g_cnt);    cnt  = (int*)p;

    cudaFuncSetAttribute(f32gemm_kernel<0, 0>,
                         cudaFuncAttributeMaxDynamicSharedMemorySize, SMEM_TOTAL);
    cudaFuncSetAttribute(f32gemm_kernel<1, 0>,
                         cudaFuncAttributeMaxDynamicSharedMemorySize, SMEM_TOTAL);
    cudaFuncSetAttribute(f32gemm_kernel<1, 1>,
                         cudaFuncAttributeMaxDynamicSharedMemorySize, SMEM_TOTAL);

    int numSMs = 148;
    cudaDeviceGetAttribute(&numSMs, cudaDevAttrMultiProcessorCount, 0);
    const int ngrid = 2 * numSMs;

    const int nElem = NB * NH;
    init_state_kernel<<<nElem / 256, 256>>>();

    // one-time transposes: x [NB][NH] -> xT [NH][NB]; W [n][k] -> WT [k][n]
    {
        dim3 tb(32, 8);
        transpose_kernel<<<dim3(NH / 32, NB / 32), tb>>>(x, xT, NB, NH);
        transpose_kernel<<<dim3(NH / 32, NH / 32), tb>>>(W1,  w1T, NH, NH);
        transpose_kernel<<<dim3(NH / 32, NH / 32), tb>>>(V1w, v1T, NH, NH);
        transpose_kernel<<<dim3(NH / 32, NH / 32), tb>>>(W2,  w2T, NH, NH);
        transpose_kernel<<<dim3(NH / 32, NH / 32), tb>>>(V2w, v2T, NH, NH);
    }

    dim3 block(256);
    int lid = 0;   // per-launch counter slot

    // cur1 = x @ W1^T + b1
    f32gemm_kernel<0, 0><<<ngrid, block, SMEM_TOTAL>>>(
        xT, w1T, b1, nullptr, nullptr, nullptr, nullptr, cur1, cnt + lid++);

    for (int st = 0; st < NSTEPS; st++) {
        const float* s1in = (st & 1) ? s1bT : s1aT;
        float*      s1out = (st & 1) ? s1aT : s1bT;
        const float* s2in = (st & 1) ? s2bT : s2aT;
        float*      s2out = (st & 1) ? s2aT : s2bT;

        // layer 1: mem1 = 0.5*mem1 + cur1 + s1in@V1w^T + V1b - reset; spike
        f32gemm_kernel<1, 0><<<ngrid, block, SMEM_TOTAL>>>(
            s1in, v1T, V1b, mem1, cur1, s1out, nullptr, nullptr, cnt + lid++);

        // cur2 = s1out @ W2^T + b2  (separately rounded)
        f32gemm_kernel<0, 0><<<ngrid, block, SMEM_TOTAL>>>(
            s1out, w2T, b2, nullptr, nullptr, nullptr, nullptr, cur2,
            cnt + lid++);

        // layer 2: mem2 = 0.5*mem2 + cur2 + s2in@V2w^T + V2b - reset;
        //          spike; ssum += spike
        f32gemm_kernel<1, 1><<<ngrid, block, SMEM_TOTAL>>>(
            s2in, v2T, V2b, mem2, cur2, s2out, ssum, nullptr, cnt + lid++);
    }

    // t = ssum/25 (rounded first), then out = t@W3^T + b3
    div25_kernel<<<nElem / 256, 256>>>(ssum);
    out_kernel<<<(NB * NO + 255) / 256, 256>>>(ssum, W3, b3, out);
}